// round 2
// baseline (speedup 1.0000x reference)
#include <cuda_runtime.h>
#include <cstdint>

// ESN: s_t = tanh(U_t + W_res @ s_{t-1}),  U = X @ W_in^T
// T=16384 steps, R=1024 reservoir, I=128 input. W_res ~5% dense.
//
// Plan per launch (all on default stream, graph-capturable, no allocs):
//   k_init  : zero ELL buffers + per-group nnz counters
//   k_build : compact W_res rows into ELL [slot][row] (val f32, col u16),
//             per-32-row-group max nnz via atomicMax
//   k_gemm  : U = X @ W_in^T into __device__ d_U (67MB static)
//   k_esn   : single 8-CTA cluster, persistent recurrence.
//             ELL slice + replicated double-buffered state in SMEM,
//             DSMEM broadcast of new state chunk, barrier.cluster per step.

#define T_STEPS 16384
#define R_DIM   1024
#define I_DIM   128
#define NCTA    8
#define RPC     128     // rows per CTA
#define NTHR    256
#define ELLCAP  192     // global ELL capacity (slots per row)
#define KCAP    128     // smem ELL capacity (slots per row)

__device__ float          d_U[(size_t)T_STEPS * R_DIM];   // 64 MiB
__device__ float          d_ellv[ELLCAP * R_DIM];
__device__ unsigned short d_ellc[ELLCAP * R_DIM];
__device__ int            d_kgrp[R_DIM / 32];             // max nnz per 32-row group

// ---------------------------------------------------------------------------
__global__ void k_init() {
    int stride = gridDim.x * blockDim.x;
    for (int i = blockIdx.x * blockDim.x + threadIdx.x; i < ELLCAP * R_DIM; i += stride) {
        d_ellv[i] = 0.0f;
        d_ellc[i] = 0;
    }
    if (blockIdx.x == 0 && threadIdx.x < R_DIM / 32) d_kgrp[threadIdx.x] = 0;
}

// One warp per reservoir row: compact nonzeros of W_res into ELL.
__global__ void k_build(const float* __restrict__ W) {
    int gw   = (blockIdx.x * blockDim.x + threadIdx.x) >> 5;  // row
    int lane = threadIdx.x & 31;
    if (gw >= R_DIM) return;
    int cnt = 0;
    for (int kb = 0; kb < R_DIM; kb += 32) {
        float w = W[(size_t)gw * R_DIM + kb + lane];
        unsigned m = __ballot_sync(0xFFFFFFFFu, w != 0.0f);
        if (w != 0.0f) {
            int pos = cnt + __popc(m & ((1u << lane) - 1u));
            if (pos < ELLCAP) {
                d_ellv[pos * R_DIM + gw] = w;
                d_ellc[pos * R_DIM + gw] = (unsigned short)(kb + lane);
            }
        }
        cnt += __popc(m);
    }
    if (lane == 0) atomicMax(&d_kgrp[gw >> 5], cnt);
}

// ---------------------------------------------------------------------------
// U = X @ W_in^T. 64x64 output tile per block, K chunked by 64.
__global__ __launch_bounds__(256) void k_gemm(const float* __restrict__ X,
                                              const float* __restrict__ Win) {
    __shared__ float xs[64][68];
    __shared__ float ws[64][68];
    int bt = blockIdx.x * 64;   // t tile
    int br = blockIdx.y * 64;   // r tile
    int ty = threadIdx.x >> 4;  // 0..15
    int tx = threadIdx.x & 15;  // 0..15

    float acc[4][4];
#pragma unroll
    for (int i = 0; i < 4; i++)
#pragma unroll
        for (int j = 0; j < 4; j++) acc[i][j] = 0.0f;

    for (int kc = 0; kc < I_DIM; kc += 64) {
        for (int i = threadIdx.x; i < 64 * 16; i += 256) {
            int r = i >> 4, c = i & 15;
            *(float4*)&xs[r][c * 4] = *(const float4*)&X[(size_t)(bt + r) * I_DIM + kc + c * 4];
            *(float4*)&ws[r][c * 4] = *(const float4*)&Win[(size_t)(br + r) * I_DIM + kc + c * 4];
        }
        __syncthreads();
#pragma unroll
        for (int k = 0; k < 64; k++) {
            float a[4], b[4];
#pragma unroll
            for (int i = 0; i < 4; i++) a[i] = xs[ty + 16 * i][k];
#pragma unroll
            for (int j = 0; j < 4; j++) b[j] = ws[tx + 16 * j][k];
#pragma unroll
            for (int i = 0; i < 4; i++)
#pragma unroll
                for (int j = 0; j < 4; j++) acc[i][j] += a[i] * b[j];
        }
        __syncthreads();
    }
#pragma unroll
    for (int i = 0; i < 4; i++)
#pragma unroll
        for (int j = 0; j < 4; j++)
            d_U[(size_t)(bt + ty + 16 * i) * R_DIM + br + tx + 16 * j] = acc[i][j];
}

// ---------------------------------------------------------------------------
// Dynamic smem layout:
//   [0)                 ellv_s : KCAP*RPC floats      (64 KiB)
//   [KCAP*RPC*4)        ellc_s : KCAP*RPC u16         (32 KiB)
//   [KCAP*RPC*6)        sbuf   : 2*R floats (double-buffered state, replicated)
//   [... + 8K)          partial: NTHR floats
#define SMEM_BYTES (KCAP * RPC * 6 + 2 * R_DIM * 4 + NTHR * 4)

__global__ __launch_bounds__(NTHR, 1) __cluster_dims__(NCTA, 1, 1)
void k_esn(const float* __restrict__ state0, float* __restrict__ out) {
    extern __shared__ unsigned char smraw[];
    float*          ellv_s  = (float*)smraw;
    unsigned short* ellc_s  = (unsigned short*)(smraw + KCAP * RPC * 4);
    float*          sbuf    = (float*)(smraw + KCAP * RPC * 6);
    float*          partial = sbuf + 2 * R_DIM;
    __shared__ int kg_s[4];

    int tid = threadIdx.x;
    int cta = blockIdx.x;  // == cluster rank (1-D single-cluster grid)

    if (tid < 4) {
        int v = d_kgrp[cta * 4 + tid];
        kg_s[tid] = v > KCAP ? KCAP : v;
    }
    for (int i = tid; i < R_DIM; i += NTHR) sbuf[i] = state0[i];
    __syncthreads();

    int Kc = max(max(kg_s[0], kg_s[1]), max(kg_s[2], kg_s[3]));
    for (int idx = tid; idx < Kc * RPC; idx += NTHR) {
        int slot = idx >> 7, lr = idx & 127;
        ellv_s[idx] = d_ellv[slot * R_DIM + cta * RPC + lr];
        ellc_s[idx] = d_ellc[slot * R_DIM + cta * RPC + lr];
    }
    __syncthreads();

    int row  = tid & 127;
    int half = tid >> 7;
    int Kg   = kg_s[row >> 5];
    int H    = (Kg + 1) >> 1;
    int kbeg = half ? H : 0;
    int kend = half ? Kg : H;

    uint32_t sb_addr;
    {
        void* p = (void*)sbuf;
        asm("{ .reg .u64 t; cvta.to.shared.u64 t, %1; cvt.u32.u64 %0, t; }"
            : "=r"(sb_addr) : "l"(p));
    }

    float u = 0.0f;
    if (tid < RPC) u = d_U[cta * RPC + tid];  // prefetch U for t=0

    for (int t = 0; t < T_STEPS; t++) {
        const float* s_rd = sbuf + (t & 1) * R_DIM;
        float acc = 0.0f;
        int k = kbeg;
        for (; k + 4 <= kend; k += 4) {
            float v0 = ellv_s[(k + 0) * RPC + row];
            float v1 = ellv_s[(k + 1) * RPC + row];
            float v2 = ellv_s[(k + 2) * RPC + row];
            float v3 = ellv_s[(k + 3) * RPC + row];
            int c0 = ellc_s[(k + 0) * RPC + row];
            int c1 = ellc_s[(k + 1) * RPC + row];
            int c2 = ellc_s[(k + 2) * RPC + row];
            int c3 = ellc_s[(k + 3) * RPC + row];
            acc += v0 * s_rd[c0];
            acc += v1 * s_rd[c1];
            acc += v2 * s_rd[c2];
            acc += v3 * s_rd[c3];
        }
        for (; k < kend; k++) acc += ellv_s[k * RPC + row] * s_rd[ellc_s[k * RPC + row]];

        partial[tid] = acc;
        __syncthreads();

        if (tid < RPC) {
            float y = u + partial[tid] + partial[tid + RPC];
            float s = tanhf(y);
            out[(size_t)t * R_DIM + cta * RPC + tid] = s;
            // broadcast into every CTA's write buffer (incl. self) via DSMEM
            uint32_t laddr = sb_addr + (uint32_t)((((t & 1) ^ 1) * R_DIM + cta * RPC + tid) * 4);
#pragma unroll
            for (int p = 0; p < NCTA; p++) {
                uint32_t raddr;
                asm("mapa.shared::cluster.u32 %0, %1, %2;" : "=r"(raddr) : "r"(laddr), "r"(p));
                asm volatile("st.shared::cluster.f32 [%0], %1;" :: "r"(raddr), "f"(s));
            }
            int tn = (t + 1 < T_STEPS) ? (t + 1) : t;
            u = d_U[(size_t)tn * R_DIM + cta * RPC + tid];  // prefetch next step's U
        }
        // release prior DSMEM stores; everyone's writes visible after wait
        asm volatile("barrier.cluster.arrive.aligned;" ::: "memory");
        asm volatile("barrier.cluster.wait.aligned;" ::: "memory");
    }
}

// ---------------------------------------------------------------------------
extern "C" void kernel_launch(void* const* d_in, const int* in_sizes, int n_in,
                              void* d_out, int out_size) {
    const float* X    = (const float*)d_in[0];  // (T, I)
    const float* Win  = (const float*)d_in[1];  // (R, I)
    const float* Wres = (const float*)d_in[2];  // (R, R)
    const float* s0   = (const float*)d_in[3];  // (R,)
    float* out = (float*)d_out;                 // (T, R)

    cudaFuncSetAttribute(k_esn, cudaFuncAttributeMaxDynamicSharedMemorySize, SMEM_BYTES);

    k_init<<<256, 256>>>();
    k_build<<<(R_DIM * 32) / 256, 256>>>(Wres);
    k_gemm<<<dim3(T_STEPS / 64, R_DIM / 64), 256>>>(X, Win);
    k_esn<<<NCTA, NTHR, SMEM_BYTES>>>(s0, out);
}

// round 3
// speedup vs baseline: 1.8607x; 1.8607x over previous
#include <cuda_runtime.h>
#include <cstdint>

// ESN: s_t = tanh(U_t + W_res @ s_{t-1}),  U = X @ W_in^T
// T=16384 steps, R=1024 reservoir, I=128 input. W_res ~5% dense.
//
// R2 changes vs R1 (25.4ms):
//  - k_build2: bank-conflict-FREE ELL schedule per 32-row group (greedy
//    distinct-bank slot assignment; pads also bank-distinct). Pair-packed
//    layout: vals float2, cols 2xu16 in u32.
//  - k_esn: mbarrier-based cluster sync (2 alternating mbarriers, remote
//    arrive w/ release + parity wait w/ acquire.cluster) instead of
//    barrier.cluster (~490cyc + L1 flush).
//  - fast tanh via exact identity 1 - 2/(exp(2y)+1).

#define T_STEPS 16384
#define R_DIM   1024
#define I_DIM   128
#define NCTA    8
#define RPC     128
#define NTHR    256
#define ELLCAP  192     // max slots per row (global)
#define KCAP    128     // max slots per row held in smem

__device__ float    d_U[(size_t)T_STEPS * R_DIM];        // 64 MiB
__device__ float2   d_ellv2[(ELLCAP / 2) * R_DIM];       // pair-packed vals
__device__ unsigned d_ellc2[(ELLCAP / 2) * R_DIM];       // pair-packed cols (2xu16)
__device__ int      d_kgrp[R_DIM / 32];                  // slots used per 32-row group (even)

__device__ __forceinline__ uint32_t smaddr(const void* p) {
    uint32_t a;
    asm("{ .reg .u64 t; cvta.to.shared.u64 t, %1; cvt.u32.u64 %0, t; }"
        : "=r"(a) : "l"(p));
    return a;
}

// ---------------------------------------------------------------------------
// Bank-conflict-free ELL build. One CTA (1 warp) per 32-row group.
// Phase 1: lane r buckets row (g*32+r)'s nonzeros by bank (col&31) into smem.
// Phase 2: lane 0 greedily fills slots; each slot's 32 picks have 32 distinct
// banks (rotating start row for fairness); unpicked rows get zero-val pads on
// the remaining free banks, so EVERY slot is fully conflict-free.
#define B2_BCOL 0
#define B2_BVAL (32 * 32 * 16 * 2)
#define B2_BCNT (B2_BVAL + 32 * 32 * 16 * 4)
#define B2_MASK (B2_BCNT + 32 * 32 * 4)
#define B2_SMEM (B2_MASK + 32 * 4)

__global__ void k_build2(const float* __restrict__ W) {
    extern __shared__ unsigned char sm[];
    unsigned short* bcol    = (unsigned short*)(sm + B2_BCOL);  // [r][b][16]
    float*          bval    = (float*)(sm + B2_BVAL);           // [r][b][16]
    int*            bcnt    = (int*)(sm + B2_BCNT);             // [r][b]
    unsigned*       rowmask = (unsigned*)(sm + B2_MASK);        // [r]

    int g = blockIdx.x;
    int r = threadIdx.x;  // 0..31

    for (int b = 0; b < 32; b++) bcnt[r * 32 + b] = 0;
    const float* Wr = W + (size_t)(g * 32 + r) * R_DIM;
    for (int c = 0; c < R_DIM; c++) {
        float w = Wr[c];
        if (w != 0.0f) {
            int b = c & 31;
            int i = bcnt[r * 32 + b]++;
            if (i < 16) {
                bcol[(r * 32 + b) * 16 + i] = (unsigned short)c;
                bval[(r * 32 + b) * 16 + i] = w;
            }
        }
    }
    unsigned m = 0;
    for (int b = 0; b < 32; b++)
        if (bcnt[r * 32 + b] > 0) m |= 1u << b;
    rowmask[r] = m;
    __syncwarp();

    if (r == 0) {
        int rows_left = 0;
        for (int i = 0; i < 32; i++)
            if (rowmask[i]) rows_left++;
        int s = 0;
        while (rows_left > 0 && s < ELLCAP) {
            unsigned used = 0, pickedmask = 0;
            for (int i = 0; i < 32; i++) {
                int rr = (s + i) & 31;
                unsigned avail = rowmask[rr] & ~used;
                if (avail) {
                    int b = __ffs(avail) - 1;
                    int c = --bcnt[rr * 32 + b];
                    unsigned short col = bcol[(rr * 32 + b) * 16 + c];
                    float v = bval[(rr * 32 + b) * 16 + c];
                    if (c == 0) {
                        rowmask[rr] &= ~(1u << b);
                        if (!rowmask[rr]) rows_left--;
                    }
                    used |= 1u << b;
                    pickedmask |= 1u << rr;
                    size_t idx = (size_t)(s >> 1) * R_DIM + g * 32 + rr;
                    ((float*)d_ellv2)[idx * 2 + (s & 1)] = v;
                    ((unsigned short*)d_ellc2)[idx * 2 + (s & 1)] = col;
                }
            }
            unsigned freeb = ~used;
            for (int rr = 0; rr < 32; rr++) {
                if (!((pickedmask >> rr) & 1)) {
                    int b = __ffs(freeb) - 1;
                    freeb &= freeb - 1;
                    size_t idx = (size_t)(s >> 1) * R_DIM + g * 32 + rr;
                    ((float*)d_ellv2)[idx * 2 + (s & 1)] = 0.0f;
                    ((unsigned short*)d_ellc2)[idx * 2 + (s & 1)] = (unsigned short)b;
                }
            }
            s++;
        }
        if (s & 1) {  // pad to even slot count; pads bank-distinct
            for (int rr = 0; rr < 32; rr++) {
                size_t idx = (size_t)(s >> 1) * R_DIM + g * 32 + rr;
                ((float*)d_ellv2)[idx * 2 + 1] = 0.0f;
                ((unsigned short*)d_ellc2)[idx * 2 + 1] = (unsigned short)rr;
            }
            s++;
        }
        d_kgrp[g] = s;
    }
}

// ---------------------------------------------------------------------------
// U = X @ W_in^T. 64x64 output tile per block, K chunked by 64.
__global__ __launch_bounds__(256) void k_gemm(const float* __restrict__ X,
                                              const float* __restrict__ Win) {
    __shared__ float xs[64][68];
    __shared__ float ws[64][68];
    int bt = blockIdx.x * 64;
    int br = blockIdx.y * 64;
    int ty = threadIdx.x >> 4;
    int tx = threadIdx.x & 15;

    float acc[4][4];
#pragma unroll
    for (int i = 0; i < 4; i++)
#pragma unroll
        for (int j = 0; j < 4; j++) acc[i][j] = 0.0f;

    for (int kc = 0; kc < I_DIM; kc += 64) {
        for (int i = threadIdx.x; i < 64 * 16; i += 256) {
            int r = i >> 4, c = i & 15;
            *(float4*)&xs[r][c * 4] = *(const float4*)&X[(size_t)(bt + r) * I_DIM + kc + c * 4];
            *(float4*)&ws[r][c * 4] = *(const float4*)&Win[(size_t)(br + r) * I_DIM + kc + c * 4];
        }
        __syncthreads();
#pragma unroll
        for (int k = 0; k < 64; k++) {
            float a[4], b[4];
#pragma unroll
            for (int i = 0; i < 4; i++) a[i] = xs[ty + 16 * i][k];
#pragma unroll
            for (int j = 0; j < 4; j++) b[j] = ws[tx + 16 * j][k];
#pragma unroll
            for (int i = 0; i < 4; i++)
#pragma unroll
                for (int j = 0; j < 4; j++) acc[i][j] += a[i] * b[j];
        }
        __syncthreads();
    }
#pragma unroll
    for (int i = 0; i < 4; i++)
#pragma unroll
        for (int j = 0; j < 4; j++)
            d_U[(size_t)(bt + ty + 16 * i) * R_DIM + br + tx + 16 * j] = acc[i][j];
}

// ---------------------------------------------------------------------------
// Dynamic smem layout (bytes):
//   [0,       65536)  ellv2 : (KCAP/2)*RPC float2
//   [65536,   98304)  ellc2 : (KCAP/2)*RPC u32
//   [98304,  106496)  sbuf  : 2*R floats (double-buffered state, replicated)
//   [106496, 107520)  partial: NTHR floats
//   [107520, 107536)  mbar[2]
#define ESN_ELLC 65536
#define ESN_SBUF 98304
#define ESN_PART 106496
#define ESN_MBAR 107520
#define SMEM_ESN 107536

__global__ __launch_bounds__(NTHR, 1) __cluster_dims__(NCTA, 1, 1)
void k_esn(const float* __restrict__ state0, float* __restrict__ out) {
    extern __shared__ unsigned char sm[];
    float2*   ellv2   = (float2*)sm;
    unsigned* ellc2   = (unsigned*)(sm + ESN_ELLC);
    float*    sbuf    = (float*)(sm + ESN_SBUF);
    float*    partial = (float*)(sm + ESN_PART);
    __shared__ int kg_s[4];

    int tid = threadIdx.x;
    int cta = blockIdx.x;  // == cluster rank (1-D single-cluster grid)

    uint32_t sb_a = smaddr(sbuf);
    uint32_t mb_a = smaddr(sm + ESN_MBAR);

    if (tid < 4) {
        int v = d_kgrp[cta * 4 + tid];
        kg_s[tid] = v > KCAP ? KCAP : v;
    }
    if (tid == 0) {
        asm volatile("mbarrier.init.shared.b64 [%0], %1;" :: "r"(mb_a), "r"(NCTA));
        asm volatile("mbarrier.init.shared.b64 [%0], %1;" :: "r"(mb_a + 8), "r"(NCTA));
    }
    for (int i = tid; i < R_DIM; i += NTHR) sbuf[i] = state0[i];
    __syncthreads();

    int Kc = max(max(kg_s[0], kg_s[1]), max(kg_s[2], kg_s[3]));
    int Kpc = Kc >> 1;
    for (int idx = tid; idx < Kpc * RPC; idx += NTHR) {
        int p = idx >> 7, lr = idx & 127;
        ellv2[idx] = d_ellv2[(size_t)p * R_DIM + cta * RPC + lr];
        ellc2[idx] = d_ellc2[(size_t)p * R_DIM + cta * RPC + lr];
    }
    __syncthreads();

    // one full cluster barrier: all CTAs' mbarrier.init complete before use
    asm volatile("barrier.cluster.arrive.aligned;" ::: "memory");
    asm volatile("barrier.cluster.wait.aligned;" ::: "memory");

    int row = tid & 127;
    int half = tid >> 7;
    int Kgp = kg_s[row >> 5] >> 1;  // pair count for this row's group
    int Hp = (Kgp + 1) >> 1;
    int kb = half ? Hp : 0;
    int ke = half ? Kgp : Hp;

    float u = 0.0f;
    if (tid < RPC) u = __ldg(&d_U[cta * RPC + tid]);  // prefetch U for t=0

    for (int t = 0; t < T_STEPS; t++) {
        const float* s_rd = sbuf + (t & 1) * R_DIM;
        float a0 = 0.0f, a1 = 0.0f;
#pragma unroll 4
        for (int k = kb; k < ke; k++) {
            float2 v = ellv2[k * RPC + row];
            unsigned c = ellc2[k * RPC + row];
            a0 += v.x * s_rd[c & 0xFFFFu];   // bank-conflict-free gathers
            a1 += v.y * s_rd[c >> 16];
        }
        float acc = a0 + a1;
        if (tid >= RPC) partial[tid] = acc;
        __syncthreads();  // S1: all state reads done; partials visible

        if (tid < RPC) {
            float y = u + acc + partial[tid + RPC];
            // tanh(y) = 1 - 2/(exp(2y)+1); exact identity, approx exp/div
            float e = __expf(2.0f * y);
            float s = 1.0f - __fdividef(2.0f, e + 1.0f);
            out[(size_t)t * R_DIM + cta * RPC + tid] = s;
            uint32_t la = sb_a + (unsigned)((((t & 1) ^ 1) * R_DIM + cta * RPC + tid) * 4);
#pragma unroll
            for (int p = 0; p < NCTA; p++) {
                uint32_t ra;
                asm("mapa.shared::cluster.u32 %0, %1, %2;" : "=r"(ra) : "r"(la), "r"(p));
                asm volatile("st.shared::cluster.f32 [%0], %1;" :: "r"(ra), "f"(s));
            }
            int tn = (t + 1 < T_STEPS) ? (t + 1) : t;
            u = __ldg(&d_U[(size_t)tn * R_DIM + cta * RPC + tid]);
        }
        __syncthreads();  // S2: DSMEM data stores program-ordered CTA-wide

        uint32_t mba = mb_a + (unsigned)((t & 1) * 8);
        if (tid == 0) {
            // release(cluster)-cumulative arrive on every CTA's mbar[t&1]:
            // publishes this CTA's data stores + read-completion
#pragma unroll
            for (int p = 0; p < NCTA; p++) {
                uint32_t ra;
                asm("mapa.shared::cluster.u32 %0, %1, %2;" : "=r"(ra) : "r"(mba), "r"(p));
                asm volatile("mbarrier.arrive.shared::cluster.b64 _, [%0];" :: "r"(ra) : "memory");
            }
        }
        unsigned parity = (t >> 1) & 1;  // each mbar flips every 2 steps
        asm volatile(
            "{ .reg .pred P;\n"
            "W%=:\n"
            " mbarrier.try_wait.parity.acquire.cluster.shared::cta.b64 P, [%0], %1, 0x989680;\n"
            " @!P bra W%=;\n"
            "}" :: "r"(mba), "r"(parity) : "memory");
    }
}

// ---------------------------------------------------------------------------
extern "C" void kernel_launch(void* const* d_in, const int* in_sizes, int n_in,
                              void* d_out, int out_size) {
    const float* X    = (const float*)d_in[0];  // (T, I)
    const float* Win  = (const float*)d_in[1];  // (R, I)
    const float* Wres = (const float*)d_in[2];  // (R, R)
    const float* s0   = (const float*)d_in[3];  // (R,)
    float* out = (float*)d_out;                 // (T, R)

    cudaFuncSetAttribute(k_build2, cudaFuncAttributeMaxDynamicSharedMemorySize, B2_SMEM);
    cudaFuncSetAttribute(k_esn, cudaFuncAttributeMaxDynamicSharedMemorySize, SMEM_ESN);

    k_build2<<<R_DIM / 32, 32, B2_SMEM>>>(Wres);
    k_gemm<<<dim3(T_STEPS / 64, R_DIM / 64), 256>>>(X, Win);
    k_esn<<<NCTA, NTHR, SMEM_ESN>>>(s0, out);
}

// round 4
// speedup vs baseline: 2.7455x; 1.4756x over previous
#include <cuda_runtime.h>
#include <cstdint>

// ESN: s_t = tanh(U_t + W_res @ s_{t-1}),  U = X @ W_in^T
// T=16384 steps, R=1024 reservoir, I=128 input. W_res ~5% dense.
//
// R3 changes vs R2 (13.66ms):
//  - k_esn: ELL vals/cols preloaded into REGISTERS (KFIX=22 pairs/thread,
//    fully unrolled); smem remainder loop for rare overflow. Crossbar/step
//    drops from ~20B/iter/thread to 8B (gathers only).
//  - k_build2 phase 1 uses float4 row scan (was scalar strided LDG).

#define T_STEPS 16384
#define R_DIM   1024
#define I_DIM   128
#define NCTA    8
#define RPC     128
#define NTHR    256
#define ELLCAP  192     // max slots per row (global)
#define KCAP    128     // max slots per row held in smem
#define KFIX    22      // register-resident pairs per thread

__device__ float    d_U[(size_t)T_STEPS * R_DIM];        // 64 MiB
__device__ float2   d_ellv2[(ELLCAP / 2) * R_DIM];       // pair-packed vals
__device__ unsigned d_ellc2[(ELLCAP / 2) * R_DIM];       // pair-packed cols (2xu16)
__device__ int      d_kgrp[R_DIM / 32];                  // slots used per 32-row group (even)

__device__ __forceinline__ uint32_t smaddr(const void* p) {
    uint32_t a;
    asm("{ .reg .u64 t; cvta.to.shared.u64 t, %1; cvt.u32.u64 %0, t; }"
        : "=r"(a) : "l"(p));
    return a;
}

// ---------------------------------------------------------------------------
// Bank-conflict-free ELL build. One CTA (1 warp) per 32-row group.
// Phase 1: lane r buckets row (g*32+r)'s nonzeros by bank (col&31) into smem.
// Phase 2: lane 0 greedily fills slots; each slot's 32 picks have 32 distinct
// banks (rotating start row for fairness); unpicked rows get zero-val pads on
// the remaining free banks, so EVERY slot is fully conflict-free.
#define B2_BCOL 0
#define B2_BVAL (32 * 32 * 16 * 2)
#define B2_BCNT (B2_BVAL + 32 * 32 * 16 * 4)
#define B2_MASK (B2_BCNT + 32 * 32 * 4)
#define B2_SMEM (B2_MASK + 32 * 4)

__global__ void k_build2(const float* __restrict__ W) {
    extern __shared__ unsigned char sm[];
    unsigned short* bcol    = (unsigned short*)(sm + B2_BCOL);  // [r][b][16]
    float*          bval    = (float*)(sm + B2_BVAL);           // [r][b][16]
    int*            bcnt    = (int*)(sm + B2_BCNT);             // [r][b]
    unsigned*       rowmask = (unsigned*)(sm + B2_MASK);        // [r]

    int g = blockIdx.x;
    int r = threadIdx.x;  // 0..31

    for (int b = 0; b < 32; b++) bcnt[r * 32 + b] = 0;
    const float4* Wr4 = (const float4*)(W + (size_t)(g * 32 + r) * R_DIM);
    for (int c4 = 0; c4 < R_DIM / 4; c4++) {
        float4 w4 = Wr4[c4];
        float wv[4] = {w4.x, w4.y, w4.z, w4.w};
#pragma unroll
        for (int j = 0; j < 4; j++) {
            float w = wv[j];
            if (w != 0.0f) {
                int c = c4 * 4 + j;
                int b = c & 31;
                int i = bcnt[r * 32 + b]++;
                if (i < 16) {
                    bcol[(r * 32 + b) * 16 + i] = (unsigned short)c;
                    bval[(r * 32 + b) * 16 + i] = w;
                }
            }
        }
    }
    unsigned m = 0;
    for (int b = 0; b < 32; b++)
        if (bcnt[r * 32 + b] > 0) m |= 1u << b;
    rowmask[r] = m;
    __syncwarp();

    if (r == 0) {
        int rows_left = 0;
        for (int i = 0; i < 32; i++)
            if (rowmask[i]) rows_left++;
        int s = 0;
        while (rows_left > 0 && s < ELLCAP) {
            unsigned used = 0, pickedmask = 0;
            for (int i = 0; i < 32; i++) {
                int rr = (s + i) & 31;
                unsigned avail = rowmask[rr] & ~used;
                if (avail) {
                    int b = __ffs(avail) - 1;
                    int c = --bcnt[rr * 32 + b];
                    unsigned short col = bcol[(rr * 32 + b) * 16 + c];
                    float v = bval[(rr * 32 + b) * 16 + c];
                    if (c == 0) {
                        rowmask[rr] &= ~(1u << b);
                        if (!rowmask[rr]) rows_left--;
                    }
                    used |= 1u << b;
                    pickedmask |= 1u << rr;
                    size_t idx = (size_t)(s >> 1) * R_DIM + g * 32 + rr;
                    ((float*)d_ellv2)[idx * 2 + (s & 1)] = v;
                    ((unsigned short*)d_ellc2)[idx * 2 + (s & 1)] = col;
                }
            }
            unsigned freeb = ~used;
            for (int rr = 0; rr < 32; rr++) {
                if (!((pickedmask >> rr) & 1)) {
                    int b = __ffs(freeb) - 1;
                    freeb &= freeb - 1;
                    size_t idx = (size_t)(s >> 1) * R_DIM + g * 32 + rr;
                    ((float*)d_ellv2)[idx * 2 + (s & 1)] = 0.0f;
                    ((unsigned short*)d_ellc2)[idx * 2 + (s & 1)] = (unsigned short)b;
                }
            }
            s++;
        }
        if (s & 1) {  // pad to even slot count; pads bank-distinct
            for (int rr = 0; rr < 32; rr++) {
                size_t idx = (size_t)(s >> 1) * R_DIM + g * 32 + rr;
                ((float*)d_ellv2)[idx * 2 + 1] = 0.0f;
                ((unsigned short*)d_ellc2)[idx * 2 + 1] = (unsigned short)rr;
            }
            s++;
        }
        d_kgrp[g] = s;
    }
}

// ---------------------------------------------------------------------------
// U = X @ W_in^T. 64x64 output tile per block, K chunked by 64.
__global__ __launch_bounds__(256) void k_gemm(const float* __restrict__ X,
                                              const float* __restrict__ Win) {
    __shared__ float xs[64][68];
    __shared__ float ws[64][68];
    int bt = blockIdx.x * 64;
    int br = blockIdx.y * 64;
    int ty = threadIdx.x >> 4;
    int tx = threadIdx.x & 15;

    float acc[4][4];
#pragma unroll
    for (int i = 0; i < 4; i++)
#pragma unroll
        for (int j = 0; j < 4; j++) acc[i][j] = 0.0f;

    for (int kc = 0; kc < I_DIM; kc += 64) {
        for (int i = threadIdx.x; i < 64 * 16; i += 256) {
            int r = i >> 4, c = i & 15;
            *(float4*)&xs[r][c * 4] = *(const float4*)&X[(size_t)(bt + r) * I_DIM + kc + c * 4];
            *(float4*)&ws[r][c * 4] = *(const float4*)&Win[(size_t)(br + r) * I_DIM + kc + c * 4];
        }
        __syncthreads();
#pragma unroll
        for (int k = 0; k < 64; k++) {
            float a[4], b[4];
#pragma unroll
            for (int i = 0; i < 4; i++) a[i] = xs[ty + 16 * i][k];
#pragma unroll
            for (int j = 0; j < 4; j++) b[j] = ws[tx + 16 * j][k];
#pragma unroll
            for (int i = 0; i < 4; i++)
#pragma unroll
                for (int j = 0; j < 4; j++) acc[i][j] += a[i] * b[j];
        }
        __syncthreads();
    }
#pragma unroll
    for (int i = 0; i < 4; i++)
#pragma unroll
        for (int j = 0; j < 4; j++)
            d_U[(size_t)(bt + ty + 16 * i) * R_DIM + br + tx + 16 * j] = acc[i][j];
}

// ---------------------------------------------------------------------------
// Dynamic smem layout (bytes):
//   [0,       65536)  ellv2 : (KCAP/2)*RPC float2
//   [65536,   98304)  ellc2 : (KCAP/2)*RPC u32
//   [98304,  106496)  sbuf  : 2*R floats (double-buffered state, replicated)
//   [106496, 107520)  partial: NTHR floats
//   [107520, 107536)  mbar[2]
#define ESN_ELLC 65536
#define ESN_SBUF 98304
#define ESN_PART 106496
#define ESN_MBAR 107520
#define SMEM_ESN 107536

__global__ __launch_bounds__(NTHR, 1) __cluster_dims__(NCTA, 1, 1)
void k_esn(const float* __restrict__ state0, float* __restrict__ out) {
    extern __shared__ unsigned char sm[];
    float2*   ellv2   = (float2*)sm;
    unsigned* ellc2   = (unsigned*)(sm + ESN_ELLC);
    float*    sbuf    = (float*)(sm + ESN_SBUF);
    float*    partial = (float*)(sm + ESN_PART);
    __shared__ int kg_s[4];

    int tid = threadIdx.x;
    int cta = blockIdx.x;  // == cluster rank (1-D single-cluster grid)

    uint32_t sb_a = smaddr(sbuf);
    uint32_t mb_a = smaddr(sm + ESN_MBAR);

    if (tid < 4) {
        int v = d_kgrp[cta * 4 + tid];
        kg_s[tid] = v > KCAP ? KCAP : v;
    }
    if (tid == 0) {
        asm volatile("mbarrier.init.shared.b64 [%0], %1;" :: "r"(mb_a), "r"(NCTA));
        asm volatile("mbarrier.init.shared.b64 [%0], %1;" :: "r"(mb_a + 8), "r"(NCTA));
    }
    for (int i = tid; i < R_DIM; i += NTHR) sbuf[i] = state0[i];
    __syncthreads();

    int Kc = max(max(kg_s[0], kg_s[1]), max(kg_s[2], kg_s[3]));
    int Kpc = Kc >> 1;
    for (int idx = tid; idx < Kpc * RPC; idx += NTHR) {
        int p = idx >> 7, lr = idx & 127;
        ellv2[idx] = d_ellv2[(size_t)p * R_DIM + cta * RPC + lr];
        ellc2[idx] = d_ellc2[(size_t)p * R_DIM + cta * RPC + lr];
    }
    __syncthreads();

    // one full cluster barrier: all CTAs' mbarrier.init complete before use
    asm volatile("barrier.cluster.arrive.aligned;" ::: "memory");
    asm volatile("barrier.cluster.wait.aligned;" ::: "memory");

    int row = tid & 127;
    int half = tid >> 7;
    int Kgp = kg_s[row >> 5] >> 1;  // pair count for this row's group
    int Hp = (Kgp + 1) >> 1;
    int kb = half ? Hp : 0;
    int ke = half ? Kgp : Hp;

    // ---- preload ELL pairs into registers (loop-invariant over t) ----
    float2   ev[KFIX];
    unsigned ec[KFIX];
    unsigned padc = (unsigned)(tid & 31);
    padc |= padc << 16;  // lane-distinct bank, zero value -> conflict-free no-op
#pragma unroll
    for (int j = 0; j < KFIX; j++) {
        int k = kb + j;
        if (k < ke) {
            ev[j] = ellv2[k * RPC + row];
            ec[j] = ellc2[k * RPC + row];
        } else {
            ev[j] = make_float2(0.0f, 0.0f);
            ec[j] = padc;
        }
    }
    int krem = kb + KFIX;  // smem remainder start (usually >= ke)

    float u = 0.0f;
    if (tid < RPC) u = __ldg(&d_U[cta * RPC + tid]);  // prefetch U for t=0

    for (int t = 0; t < T_STEPS; t++) {
        const float* s_rd = sbuf + (t & 1) * R_DIM;
        float a0 = 0.0f, a1 = 0.0f;
#pragma unroll
        for (int j = 0; j < KFIX; j++) {
            unsigned c = ec[j];
            a0 += ev[j].x * s_rd[c & 0xFFFFu];   // bank-conflict-free gathers
            a1 += ev[j].y * s_rd[c >> 16];
        }
        for (int k = krem; k < ke; k++) {  // rare overflow pairs from smem
            float2 v = ellv2[k * RPC + row];
            unsigned c = ellc2[k * RPC + row];
            a0 += v.x * s_rd[c & 0xFFFFu];
            a1 += v.y * s_rd[c >> 16];
        }
        float acc = a0 + a1;
        if (tid >= RPC) partial[tid] = acc;
        __syncthreads();  // S1: all state reads done; partials visible

        if (tid < RPC) {
            float y = u + acc + partial[tid + RPC];
            // tanh(y) = 1 - 2/(exp(2y)+1); exact identity, approx exp/div
            float e = __expf(2.0f * y);
            float s = 1.0f - __fdividef(2.0f, e + 1.0f);
            out[(size_t)t * R_DIM + cta * RPC + tid] = s;
            uint32_t la = sb_a + (unsigned)((((t & 1) ^ 1) * R_DIM + cta * RPC + tid) * 4);
#pragma unroll
            for (int p = 0; p < NCTA; p++) {
                uint32_t ra;
                asm("mapa.shared::cluster.u32 %0, %1, %2;" : "=r"(ra) : "r"(la), "r"(p));
                asm volatile("st.shared::cluster.f32 [%0], %1;" :: "r"(ra), "f"(s));
            }
            int tn = (t + 1 < T_STEPS) ? (t + 1) : t;
            u = __ldg(&d_U[(size_t)tn * R_DIM + cta * RPC + tid]);
        }
        __syncthreads();  // S2: DSMEM data stores program-ordered CTA-wide

        uint32_t mba = mb_a + (unsigned)((t & 1) * 8);
        if (tid == 0) {
            // release(cluster)-cumulative arrive on every CTA's mbar[t&1]:
            // publishes this CTA's data stores + read-completion
#pragma unroll
            for (int p = 0; p < NCTA; p++) {
                uint32_t ra;
                asm("mapa.shared::cluster.u32 %0, %1, %2;" : "=r"(ra) : "r"(mba), "r"(p));
                asm volatile("mbarrier.arrive.shared::cluster.b64 _, [%0];" :: "r"(ra) : "memory");
            }
        }
        unsigned parity = (t >> 1) & 1;  // each mbar flips every 2 steps
        asm volatile(
            "{ .reg .pred P;\n"
            "W%=:\n"
            " mbarrier.try_wait.parity.acquire.cluster.shared::cta.b64 P, [%0], %1, 0x989680;\n"
            " @!P bra W%=;\n"
            "}" :: "r"(mba), "r"(parity) : "memory");
    }
}

// ---------------------------------------------------------------------------
extern "C" void kernel_launch(void* const* d_in, const int* in_sizes, int n_in,
                              void* d_out, int out_size) {
    const float* X    = (const float*)d_in[0];  // (T, I)
    const float* Win  = (const float*)d_in[1];  // (R, I)
    const float* Wres = (const float*)d_in[2];  // (R, R)
    const float* s0   = (const float*)d_in[3];  // (R,)
    float* out = (float*)d_out;                 // (T, R)

    cudaFuncSetAttribute(k_build2, cudaFuncAttributeMaxDynamicSharedMemorySize, B2_SMEM);
    cudaFuncSetAttribute(k_esn, cudaFuncAttributeMaxDynamicSharedMemorySize, SMEM_ESN);

    k_build2<<<R_DIM / 32, 32, B2_SMEM>>>(Wres);
    k_gemm<<<dim3(T_STEPS / 64, R_DIM / 64), 256>>>(X, Win);
    k_esn<<<NCTA, NTHR, SMEM_ESN>>>(s0, out);
}